// round 13
// baseline (speedup 1.0000x reference)
#include <cuda_runtime.h>
#include <cuda_bf16.h>
#include <cuda_fp16.h>
#include <math.h>
#include <stdint.h>

// Problem constants
#define D_MODEL 1024
#define N_HEADS 16
#define D_HEAD  64
#define BATCH   4
#define SEQ     512
#define M_TOK   (BATCH * SEQ)       // 2048
#define QKV_N   (3 * D_MODEL)       // 3072
#define BHN     (BATCH * N_HEADS)   // 64
#define QS      (BHN * SEQ * D_HEAD) // 2097152

// ---------------- device scratch (no runtime allocation allowed) ----------------
__device__ float g_rope_cos[SEQ * D_HEAD];
__device__ float g_rope_sin[SEQ * D_HEAD];

// bf16 hi/lo splits for projection GEMMs
#define XN   (M_TOK * D_MODEL)      // 2097152
#define WQN  (QKV_N * D_MODEL)      // 3145728
#define WON  (D_MODEL * D_MODEL)    // 1048576
__device__ __nv_bfloat16 g_xrH[XN],  g_xrL[XN],  g_xiH[XN],  g_xiL[XN];
__device__ __nv_bfloat16 g_wqrH[WQN], g_wqrL[WQN], g_wqiH[WQN], g_wqiL[WQN];
__device__ __nv_bfloat16 g_worH[WON], g_worL[WON], g_woiH[WON], g_woiL[WON];
__device__ __nv_bfloat16 g_arH[XN],  g_arL[XN],  g_aiH[XN],  g_aiL[XN];

// attention operands (written by fused QKV-GEMM epilogue)
// Q, K: bf16 hi/lo, [bh][s][d] token-major, Q pre-scaled by 1/8.
// V: single fp16, [bh][d][s] dim-major (transposed, B-frag ready).
__device__ __nv_bfloat16 g_QrH[QS], g_QrL[QS], g_QiH[QS], g_QiL[QS];
__device__ __nv_bfloat16 g_KrH[QS], g_KrL[QS], g_KiH[QS], g_KiL[QS];
__device__ __half g_VrF[QS], g_ViF[QS];

// ================= PTX helpers (baseline ISA only — no tcgen05) =================
__device__ __forceinline__ uint32_t smem_u32(const void* p) {
    uint32_t a;
    asm("{ .reg .u64 t; cvta.to.shared.u64 t, %1; cvt.u32.u64 %0, t; }" : "=r"(a) : "l"(p));
    return a;
}
__device__ __forceinline__ void cp_async16(uint32_t dst, const void* src) {
    asm volatile("cp.async.cg.shared.global [%0], [%1], 16;" :: "r"(dst), "l"(src));
}
__device__ __forceinline__ void cp_commit() {
    asm volatile("cp.async.commit_group;" ::: "memory");
}
template <int N> __device__ __forceinline__ void cp_wait() {
    asm volatile("cp.async.wait_group %0;" :: "n"(N) : "memory");
}
__device__ __forceinline__ void ldsm_x4(uint32_t* r, uint32_t a) {
    asm volatile("ldmatrix.sync.aligned.m8n8.x4.shared.b16 {%0,%1,%2,%3}, [%4];"
                 : "=r"(r[0]), "=r"(r[1]), "=r"(r[2]), "=r"(r[3]) : "r"(a));
}
// D += A(16x16 bf16, row) * B(16x8 bf16, col), fp32 accumulate
__device__ __forceinline__ void mma_bf16(float* c, const uint32_t* a, const uint32_t* b) {
    asm volatile(
        "mma.sync.aligned.m16n8k16.row.col.f32.bf16.bf16.f32 "
        "{%0,%1,%2,%3}, {%4,%5,%6,%7}, {%8,%9}, {%0,%1,%2,%3};"
        : "+f"(c[0]), "+f"(c[1]), "+f"(c[2]), "+f"(c[3])
        : "r"(a[0]), "r"(a[1]), "r"(a[2]), "r"(a[3]), "r"(b[0]), "r"(b[1]));
}
// D += A(16x16 f16, row) * B(16x8 f16, col), fp32 accumulate
__device__ __forceinline__ void mma_f16(float* c, const uint32_t* a, const uint32_t* b) {
    asm volatile(
        "mma.sync.aligned.m16n8k16.row.col.f32.f16.f16.f32 "
        "{%0,%1,%2,%3}, {%4,%5,%6,%7}, {%8,%9}, {%0,%1,%2,%3};"
        : "+f"(c[0]), "+f"(c[1]), "+f"(c[2]), "+f"(c[3])
        : "r"(a[0]), "r"(a[1]), "r"(a[2]), "r"(a[3]), "r"(b[0]), "r"(b[1]));
}
__device__ __forceinline__ void bsplit(float v, __nv_bfloat16& h, __nv_bfloat16& l) {
    h = __float2bfloat16_rn(v);
    l = __float2bfloat16_rn(v - __bfloat162float(h));
}
__device__ __forceinline__ uint32_t packbf2(__nv_bfloat16 a, __nv_bfloat16 b) {
    __nv_bfloat162 t{a, b};
    return *reinterpret_cast<uint32_t*>(&t);
}
__device__ __forceinline__ uint32_t packh2(float a, float b) {
    __half2 t{__float2half_rn(a), __float2half_rn(b)};
    return *reinterpret_cast<uint32_t*>(&t);
}
#define SGNX2 0x80008000u

// ---------------- kernel 1: RoPE rotor table ----------------
__global__ void rope_table_kernel() {
    int i = blockIdx.x * blockDim.x + threadIdx.x;
    if (i >= SEQ * D_HEAD) return;
    int s = i / D_HEAD;
    int d = i % D_HEAD;
    float inv_freq = powf(10000.0f, -(float)d / (float)D_HEAD);
    float ang = (float)s * inv_freq;
    float sn, cs;
    sincosf(ang, &sn, &cs);
    g_rope_cos[i] = cs;
    g_rope_sin[i] = sn;
}

// ---------------- kernel 1b: complex hi/lo split (re, im) ----------------
__global__ void split_cx_kernel(const float* __restrict__ re, const float* __restrict__ im,
                                __nv_bfloat16* __restrict__ rH, __nv_bfloat16* __restrict__ rL,
                                __nv_bfloat16* __restrict__ iH, __nv_bfloat16* __restrict__ iL,
                                int n4) {
    int i = blockIdx.x * blockDim.x + threadIdx.x;
    if (i >= n4) return;
    float4 vr = ((const float4*)re)[i];
    float4 vi = ((const float4*)im)[i];
    __nv_bfloat16 h0, h1, h2, h3, l0, l1, l2, l3;

    bsplit(vr.x, h0, l0); bsplit(vr.y, h1, l1); bsplit(vr.z, h2, l2); bsplit(vr.w, h3, l3);
    ((uint32_t*)rH)[i * 2 + 0] = packbf2(h0, h1);
    ((uint32_t*)rH)[i * 2 + 1] = packbf2(h2, h3);
    ((uint32_t*)rL)[i * 2 + 0] = packbf2(l0, l1);
    ((uint32_t*)rL)[i * 2 + 1] = packbf2(l2, l3);

    bsplit(vi.x, h0, l0); bsplit(vi.y, h1, l1); bsplit(vi.z, h2, l2); bsplit(vi.w, h3, l3);
    ((uint32_t*)iH)[i * 2 + 0] = packbf2(h0, h1);
    ((uint32_t*)iH)[i * 2 + 1] = packbf2(h2, h3);
    ((uint32_t*)iL)[i * 2 + 0] = packbf2(l0, l1);
    ((uint32_t*)iL)[i * 2 + 1] = packbf2(l2, l3);
}

// ---------------- kernel 2: mma.sync complex GEMM  C = A @ B^T ----------------
// Direct form (12 HMMA per micro-tile). CTA tile 128x128, K-stage 32, 2-stage
// cp.async, 8 warps (4m x 2n), warp tile 32x64.
// FUSE_ROPE epilogue: RoPE + head-split + Q/K bf16 splits (Q pre-scaled) + V fp16.
#define GBM 128
#define GBN 128
#define GBK 32
#define GPITCHB 80
#define A_COMP_B (GBM * GPITCHB)              // 10240
#define B_COMP_B (GBN * GPITCHB)              // 10240
#define STAGE_B  (4 * A_COMP_B + 4 * B_COMP_B) // 81920
#define G_SMEM   (2 * STAGE_B)                 // 163840

template <bool FUSE_ROPE>
__global__ __launch_bounds__(256, 1) void cgemm_tc_kernel(
    const __nv_bfloat16* __restrict__ ArH, const __nv_bfloat16* __restrict__ ArL,
    const __nv_bfloat16* __restrict__ AiH, const __nv_bfloat16* __restrict__ AiL,
    const __nv_bfloat16* __restrict__ BrH, const __nv_bfloat16* __restrict__ BrL,
    const __nv_bfloat16* __restrict__ BiH, const __nv_bfloat16* __restrict__ BiL,
    float* __restrict__ Cre, float* __restrict__ Cim,
    int N, int K)
{
    extern __shared__ __align__(128) char smem[];
    const uint32_t sb = smem_u32(smem);
    const int tid = threadIdx.x;
    const int lane = tid & 31;
    const int wid = tid >> 5;
    const int wm = wid & 3;
    const int wn = wid >> 2;
    const int m0 = blockIdx.y * GBM;
    const int n0 = blockIdx.x * GBN;

    const __nv_bfloat16* Ap[4] = {ArH, ArL, AiH, AiL};
    const __nv_bfloat16* Bp[4] = {BrH, BrL, BiH, BiL};

    auto load_stage = [&](int st, int k0) {
        uint32_t base = sb + st * STAGE_B;
#pragma unroll
        for (int i = 0; i < 8; i++) {
            int idx = tid + i * 256;
            int comp = idx >> 9;
            int rem = idx & 511;
            int row = rem >> 2;
            int ch = rem & 3;
            cp_async16(base + comp * A_COMP_B + row * GPITCHB + ch * 16,
                       Ap[comp] + (size_t)(m0 + row) * K + k0 + ch * 8);
        }
        uint32_t bbase = base + 4 * A_COMP_B;
#pragma unroll
        for (int i = 0; i < 8; i++) {
            int idx = tid + i * 256;
            int comp = idx >> 9;
            int rem = idx & 511;
            int row = rem >> 2;
            int ch = rem & 3;
            cp_async16(bbase + comp * B_COMP_B + row * GPITCHB + ch * 16,
                       Bp[comp] + (size_t)(n0 + row) * K + k0 + ch * 8);
        }
        cp_commit();
    };

    float cre[2][8][4];
    float cim[2][8][4];
#pragma unroll
    for (int mt = 0; mt < 2; mt++)
#pragma unroll
        for (int nt = 0; nt < 8; nt++)
#pragma unroll
            for (int q = 0; q < 4; q++) { cre[mt][nt][q] = 0.f; cim[mt][nt][q] = 0.f; }

    const int NC = K / GBK;
    load_stage(0, 0);

    const uint32_t krow = ((lane >> 4) & 1) * 8 + (lane & 7);
    const uint32_t koff = ((lane >> 3) & 1) * 16;

    for (int c = 0; c < NC; c++) {
        if (c + 1 < NC) { load_stage((c + 1) & 1, (c + 1) * GBK); cp_wait<1>(); }
        else            { cp_wait<0>(); }
        __syncthreads();

        const uint32_t abase = sb + (c & 1) * STAGE_B;
        const uint32_t bbase = abase + 4 * A_COMP_B;

#pragma unroll
        for (int ks = 0; ks < 2; ks++) {
            uint32_t af[4][2][4];
#pragma unroll
            for (int comp = 0; comp < 4; comp++)
#pragma unroll
                for (int mt = 0; mt < 2; mt++) {
                    uint32_t addr = abase + comp * A_COMP_B
                        + (uint32_t)(wm * 32 + mt * 16 + (lane & 15)) * GPITCHB
                        + ks * 32 + (lane >> 4) * 16;
                    ldsm_x4(af[comp][mt], addr);
                }
#pragma unroll
            for (int nt16 = 0; nt16 < 4; nt16++) {
                uint32_t bfr[4][4];
                uint32_t baddr = bbase
                    + (uint32_t)(wn * 64 + nt16 * 16 + krow) * GPITCHB
                    + ks * 32 + koff;
#pragma unroll
                for (int comp = 0; comp < 4; comp++)
                    ldsm_x4(bfr[comp], baddr + comp * B_COMP_B);
#pragma unroll
                for (int hf = 0; hf < 2; hf++) {
                    int nt = nt16 * 2 + hf;
                    const uint32_t* bRH = bfr[0] + hf * 2;
                    const uint32_t* bRL = bfr[1] + hf * 2;
                    const uint32_t* bIH = bfr[2] + hf * 2;
                    const uint32_t* bIL = bfr[3] + hf * 2;
                    uint32_t nIH[2] = {bIH[0] ^ SGNX2, bIH[1] ^ SGNX2};
                    uint32_t nIL[2] = {bIL[0] ^ SGNX2, bIL[1] ^ SGNX2};
#pragma unroll
                    for (int mt = 0; mt < 2; mt++) {
                        float* cr = cre[mt][nt];
                        float* ci = cim[mt][nt];
                        mma_bf16(cr, af[0][mt], bRH);
                        mma_bf16(cr, af[0][mt], bRL);
                        mma_bf16(cr, af[1][mt], bRH);
                        mma_bf16(cr, af[2][mt], nIH);
                        mma_bf16(cr, af[2][mt], nIL);
                        mma_bf16(cr, af[3][mt], nIH);
                        mma_bf16(ci, af[0][mt], bIH);
                        mma_bf16(ci, af[0][mt], bIL);
                        mma_bf16(ci, af[1][mt], bIH);
                        mma_bf16(ci, af[2][mt], bRH);
                        mma_bf16(ci, af[2][mt], bRL);
                        mma_bf16(ci, af[3][mt], bRH);
                    }
                }
            }
        }
        __syncthreads();
    }

    // ---- epilogue ----
#pragma unroll
    for (int mt = 0; mt < 2; mt++) {
        int row0 = m0 + wm * 32 + mt * 16 + (lane >> 2);
#pragma unroll
        for (int nt = 0; nt < 8; nt++) {
            int col = n0 + wn * 64 + nt * 8 + (lane & 3) * 2;
            if (!FUSE_ROPE) {
                *(float2*)(Cre + (size_t)row0 * N + col) = {cre[mt][nt][0], cre[mt][nt][1]};
                *(float2*)(Cre + (size_t)(row0 + 8) * N + col) = {cre[mt][nt][2], cre[mt][nt][3]};
                *(float2*)(Cim + (size_t)row0 * N + col) = {cim[mt][nt][0], cim[mt][nt][1]};
                *(float2*)(Cim + (size_t)(row0 + 8) * N + col) = {cim[mt][nt][2], cim[mt][nt][3]};
            } else {
                int sec = col >> 10;          // 0=Q, 1=K, 2=V
                int hd = col & 1023;
                int h = hd >> 6;
                int d = hd & 63;
#pragma unroll
                for (int half = 0; half < 2; half++) {
                    int tkn = row0 + half * 8;
                    int b = tkn >> 9;
                    int s = tkn & 511;
                    int bh = (b << 4) + h;
                    float re0 = cre[mt][nt][half * 2 + 0];
                    float re1 = cre[mt][nt][half * 2 + 1];
                    float im0 = cim[mt][nt][half * 2 + 0];
                    float im1 = cim[mt][nt][half * 2 + 1];
                    if (sec == 2) {
                        size_t j = (size_t)bh * 32768 + (size_t)d * 512 + s;
                        g_VrF[j] = __float2half_rn(re0);
                        g_ViF[j] = __float2half_rn(im0);
                        g_VrF[j + 512] = __float2half_rn(re1);
                        g_ViF[j + 512] = __float2half_rn(im1);
                    } else {
                        float2 rc = *(const float2*)(g_rope_cos + s * 64 + d);
                        float2 rs = *(const float2*)(g_rope_sin + s * 64 + d);
                        float ar0 = re0 * rc.x - im0 * rs.x;
                        float ai0 = re0 * rs.x + im0 * rc.x;
                        float ar1 = re1 * rc.y - im1 * rs.y;
                        float ai1 = re1 * rs.y + im1 * rc.y;
                        size_t i = (size_t)bh * 32768 + s * 64 + d;
                        __nv_bfloat16 h0, l0, h1, l1;
                        if (sec == 0) {
                            ar0 *= 0.125f; ai0 *= 0.125f; ar1 *= 0.125f; ai1 *= 0.125f;
                            bsplit(ar0, h0, l0); bsplit(ar1, h1, l1);
                            *(uint32_t*)(g_QrH + i) = packbf2(h0, h1);
                            *(uint32_t*)(g_QrL + i) = packbf2(l0, l1);
                            bsplit(ai0, h0, l0); bsplit(ai1, h1, l1);
                            *(uint32_t*)(g_QiH + i) = packbf2(h0, h1);
                            *(uint32_t*)(g_QiL + i) = packbf2(l0, l1);
                        } else {
                            bsplit(ar0, h0, l0); bsplit(ar1, h1, l1);
                            *(uint32_t*)(g_KrH + i) = packbf2(h0, h1);
                            *(uint32_t*)(g_KrL + i) = packbf2(l0, l1);
                            bsplit(ai0, h0, l0); bsplit(ai1, h1, l1);
                            *(uint32_t*)(g_KiH + i) = packbf2(h0, h1);
                            *(uint32_t*)(g_KiL + i) = packbf2(l0, l1);
                        }
                    }
                }
            }
        }
    }
}

// ---------------- kernel 4: tensor-core flash attention (complex) ----------------
// CTA: 128 queries x one (b,h). 8 warps, warp w owns rows w*16..w*16+15.
// Q-hi fragments live in registers (loaded once); Q-lo in a small persistent
// smem region; K/V in a 3-stage cp.async pipeline.
#define AP    144
#define KCOMP (64 * AP)                    // 9216
#define QLO_BYTES (4 * KCOMP)              // QrL + QiL, 128 rows each
#define ASTAGE   (6 * KCOMP)               // 4 K bf16 comps + 2 V fp16 comps
#define A_SMEM   (QLO_BYTES + 3 * ASTAGE)  // 202752

__global__ __launch_bounds__(256, 1) void attn_tc_kernel() {
    extern __shared__ __align__(128) char smem[];
    const uint32_t sb = smem_u32(smem);          // QrL at sb, QiL at sb+2*KCOMP
    const uint32_t sbKV = sb + QLO_BYTES;        // 3 stages of 6*KCOMP
    const int tid = threadIdx.x;
    const int lane = tid & 31;
    const int w = tid >> 5;
    const int grp = lane >> 2;
    const int tq = lane & 3;
    const int q0 = blockIdx.x * 128;
    const int bh = blockIdx.y;

    const __nv_bfloat16* gK[4] = {g_KrH, g_KrL, g_KiH, g_KiL};
    const __half* gV[2] = {g_VrF, g_ViF};
    const size_t hbQ = (size_t)bh * (SEQ * 64);

    // ---- prologue group A: all Q comps (hi comps staged via stage-0 region) ----
    {
        const __nv_bfloat16* gQ[4] = {g_QrH, g_QiH, g_QrL, g_QiL};
        uint32_t dstb[4] = {sbKV, sbKV + 2 * KCOMP, sb, sb + 2 * KCOMP};
#pragma unroll
        for (int it = 0; it < 16; it++) {
            int idx = tid + it * 256;
            int comp = idx >> 10;
            int rem = idx & 1023;
            int row = rem >> 3;
            int ch = rem & 7;
            cp_async16(dstb[comp] + row * AP + ch * 16,
                       gQ[comp] + hbQ + (size_t)(q0 + row) * 64 + ch * 8);
        }
        cp_commit();
    }

    auto load_stage = [&](int st, int c0) {
        uint32_t base = sbKV + st * ASTAGE;
#pragma unroll
        for (int it = 0; it < 12; it++) {
            int idx = tid + it * 256;
            int comp = idx >> 9;              // 0..5
            int rem = idx & 511;
            int row = rem >> 3;
            int ch = rem & 7;
            const void* src;
            if (comp < 4) src = gK[comp] + hbQ + (size_t)(c0 + row) * 64 + ch * 8;
            else          src = gV[comp - 4] + hbQ + (size_t)row * SEQ + c0 + ch * 8;
            cp_async16(base + comp * KCOMP + row * AP + ch * 16, src);
        }
        cp_commit();
    };

    // group B: kc0 -> buf2
    load_stage(2, 0);
    cp_wait<1>();          // Q done (kc0 may still be in flight)
    __syncthreads();

    // ldsm Q-hi fragments into registers (reused across all 8 key-blocks)
    uint32_t qrH[4][4], qiH[4][4];
#pragma unroll
    for (int ks = 0; ks < 4; ks++) {
        uint32_t qa = (uint32_t)(w * 16 + (lane & 15)) * AP + ks * 32 + (lane >> 4) * 16;
        ldsm_x4(qrH[ks], sbKV + qa);
        ldsm_x4(qiH[ks], sbKV + 2 * KCOMP + qa);
    }
    __syncthreads();       // stage-0 region free for K/V reuse

    // group C: kc1 -> buf0 (overwrites Q-hi staging)
    load_stage(0, 64);

    float or_[8][4], oi_[8][4];
#pragma unroll
    for (int nt = 0; nt < 8; nt++)
#pragma unroll
        for (int q = 0; q < 4; q++) { or_[nt][q] = 0.f; oi_[nt][q] = 0.f; }
    float m0 = -1e30f, m1 = -1e30f, l0 = 0.f, l1 = 0.f;

    const uint32_t krow = ((lane >> 4) & 1) * 8 + (lane & 7);
    const uint32_t koff = ((lane >> 3) & 1) * 16;

    for (int kc = 0; kc < 8; kc++) {
        // issue kc+2 into buffer (kc+1)%3 (holds kc-1's consumed data)
        if (kc + 2 < 8) { load_stage((kc + 1) % 3, (kc + 2) * 64); cp_wait<2>(); }
        else if (kc + 1 < 8) cp_wait<1>();
        else cp_wait<0>();
        __syncthreads();
        const uint32_t stg = sbKV + ((kc + 2) % 3) * ASTAGE;

        float sre[8][4], sim[8][4];
#pragma unroll
        for (int nt = 0; nt < 8; nt++)
#pragma unroll
            for (int q = 0; q < 4; q++) { sre[nt][q] = 0.f; sim[nt][q] = 0.f; }

#pragma unroll
        for (int ks = 0; ks < 4; ks++) {
            uint32_t qa = (uint32_t)(w * 16 + (lane & 15)) * AP + ks * 32 + (lane >> 4) * 16;
            uint32_t qrL[4], qiL[4];
            ldsm_x4(qrL, sb + qa);
            ldsm_x4(qiL, sb + 2 * KCOMP + qa);
#pragma unroll
            for (int nt16 = 0; nt16 < 4; nt16++) {
                uint32_t kb = stg + (uint32_t)(nt16 * 16 + krow) * AP + ks * 32 + koff;
                uint32_t krH[4], krL[4], kiH[4], kiL[4];
                ldsm_x4(krH, kb + 0 * KCOMP);
                ldsm_x4(krL, kb + 1 * KCOMP);
                ldsm_x4(kiH, kb + 2 * KCOMP);
                ldsm_x4(kiL, kb + 3 * KCOMP);
#pragma unroll
                for (int hf = 0; hf < 2; hf++) {
                    int nt = nt16 * 2 + hf;
                    const uint32_t* bRH = krH + hf * 2;
                    const uint32_t* bRL = krL + hf * 2;
                    const uint32_t* bIH = kiH + hf * 2;
                    const uint32_t* bIL = kiL + hf * 2;
                    uint32_t nIH[2] = {bIH[0] ^ SGNX2, bIH[1] ^ SGNX2};
                    uint32_t nIL[2] = {bIL[0] ^ SGNX2, bIL[1] ^ SGNX2};
                    mma_bf16(sre[nt], qrH[ks], bRH);
                    mma_bf16(sre[nt], qrH[ks], bRL);
                    mma_bf16(sre[nt], qrL, bRH);
                    mma_bf16(sre[nt], qiH[ks], bIH);
                    mma_bf16(sre[nt], qiH[ks], bIL);
                    mma_bf16(sre[nt], qiL, bIH);
                    mma_bf16(sim[nt], qiH[ks], bRH);
                    mma_bf16(sim[nt], qiH[ks], bRL);
                    mma_bf16(sim[nt], qiL, bRH);
                    mma_bf16(sim[nt], qrH[ks], nIH);
                    mma_bf16(sim[nt], qrH[ks], nIL);
                    mma_bf16(sim[nt], qrL, nIH);
                }
            }
        }

        // (scale folded into Q at the QKV epilogue)
        float cx0 = -1e30f, cx1 = -1e30f;
#pragma unroll
        for (int nt = 0; nt < 8; nt++) {
            cx0 = fmaxf(cx0, fmaxf(sre[nt][0], sre[nt][1]));
            cx1 = fmaxf(cx1, fmaxf(sre[nt][2], sre[nt][3]));
        }
        cx0 = fmaxf(cx0, __shfl_xor_sync(0xffffffffu, cx0, 1));
        cx0 = fmaxf(cx0, __shfl_xor_sync(0xffffffffu, cx0, 2));
        cx1 = fmaxf(cx1, __shfl_xor_sync(0xffffffffu, cx1, 1));
        cx1 = fmaxf(cx1, __shfl_xor_sync(0xffffffffu, cx1, 2));

        float nm0 = fmaxf(m0, cx0), nm1 = fmaxf(m1, cx1);
        float al0 = __expf(m0 - nm0), al1 = __expf(m1 - nm1);
        m0 = nm0; m1 = nm1;

        float rs0 = 0.f, rs1 = 0.f;
#pragma unroll
        for (int nt = 0; nt < 8; nt++) {
            float p0 = __expf(sre[nt][0] - nm0);
            float p1 = __expf(sre[nt][1] - nm0);
            float p2 = __expf(sre[nt][2] - nm1);
            float p3 = __expf(sre[nt][3] - nm1);
            rs0 += p0 + p1; rs1 += p2 + p3;
            float sn, cs;
            __sincosf(sim[nt][0], &sn, &cs); sre[nt][0] = p0 * cs; sim[nt][0] = p0 * sn;
            __sincosf(sim[nt][1], &sn, &cs); sre[nt][1] = p1 * cs; sim[nt][1] = p1 * sn;
            __sincosf(sim[nt][2], &sn, &cs); sre[nt][2] = p2 * cs; sim[nt][2] = p2 * sn;
            __sincosf(sim[nt][3], &sn, &cs); sre[nt][3] = p3 * cs; sim[nt][3] = p3 * sn;
        }
        rs0 += __shfl_xor_sync(0xffffffffu, rs0, 1);
        rs0 += __shfl_xor_sync(0xffffffffu, rs0, 2);
        rs1 += __shfl_xor_sync(0xffffffffu, rs1, 1);
        rs1 += __shfl_xor_sync(0xffffffffu, rs1, 2);
        l0 = l0 * al0 + rs0;
        l1 = l1 * al1 + rs1;
#pragma unroll
        for (int nt = 0; nt < 8; nt++) {
            or_[nt][0] *= al0; or_[nt][1] *= al0; or_[nt][2] *= al1; or_[nt][3] *= al1;
            oi_[nt][0] *= al0; oi_[nt][1] *= al0; oi_[nt][2] *= al1; oi_[nt][3] *= al1;
        }

        uint32_t wcF[4][4], wsF[4][4];
#pragma unroll
        for (int t = 0; t < 4; t++)
#pragma unroll
            for (int r = 0; r < 4; r++) {
                int nt = 2 * t + (r >> 1);
                int e = (r & 1) * 2;
                wcF[t][r] = packh2(sre[nt][e], sre[nt][e + 1]);
                wsF[t][r] = packh2(sim[nt][e], sim[nt][e + 1]);
            }

#pragma unroll
        for (int ks = 0; ks < 4; ks++) {
#pragma unroll
            for (int nt16 = 0; nt16 < 4; nt16++) {
                uint32_t vb = stg + (uint32_t)(nt16 * 16 + krow) * AP + ks * 32 + koff;
                uint32_t vrF[4], viF[4];
                ldsm_x4(vrF, vb + 4 * KCOMP);
                ldsm_x4(viF, vb + 5 * KCOMP);
#pragma unroll
                for (int hf = 0; hf < 2; hf++) {
                    int nt = nt16 * 2 + hf;
                    const uint32_t* bRF = vrF + hf * 2;
                    const uint32_t* bIF = viF + hf * 2;
                    uint32_t nIF[2] = {bIF[0] ^ SGNX2, bIF[1] ^ SGNX2};
                    mma_f16(or_[nt], wcF[ks], bRF);
                    mma_f16(or_[nt], wsF[ks], nIF);
                    mma_f16(oi_[nt], wcF[ks], bIF);
                    mma_f16(oi_[nt], wsF[ks], bRF);
                }
            }
        }
        __syncthreads();
    }

    // ---- epilogue: emit bf16 hi/lo splits for output projection ----
    int b = bh >> 4;
    int h = bh & 15;
    float inv0 = 1.0f / l0, inv1 = 1.0f / l1;
    int qr0 = q0 + w * 16 + grp;
#pragma unroll
    for (int nt = 0; nt < 8; nt++) {
        int col = h * 64 + nt * 8 + tq * 2;
        size_t r0 = (size_t)(b * SEQ + qr0) * D_MODEL + col;
        size_t r1 = (size_t)(b * SEQ + qr0 + 8) * D_MODEL + col;
#pragma unroll
        for (int half = 0; half < 2; half++) {
            size_t rr = half ? r1 : r0;
            float inv = half ? inv1 : inv0;
            float ar0 = or_[nt][half * 2 + 0] * inv;
            float ar1 = or_[nt][half * 2 + 1] * inv;
            float ai0 = oi_[nt][half * 2 + 0] * inv;
            float ai1 = oi_[nt][half * 2 + 1] * inv;
            __nv_bfloat16 h0, lo0, h1, lo1;
            bsplit(ar0, h0, lo0); bsplit(ar1, h1, lo1);
            *(uint32_t*)(g_arH + rr) = packbf2(h0, h1);
            *(uint32_t*)(g_arL + rr) = packbf2(lo0, lo1);
            bsplit(ai0, h0, lo0); bsplit(ai1, h1, lo1);
            *(uint32_t*)(g_aiH + rr) = packbf2(h0, h1);
            *(uint32_t*)(g_aiL + rr) = packbf2(lo0, lo1);
        }
    }
}

// ---------------- launch ----------------
extern "C" void kernel_launch(void* const* d_in, const int* in_sizes, int n_in,
                              void* d_out, int out_size) {
    (void)in_sizes; (void)n_in; (void)out_size;
    const float* x_re    = (const float*)d_in[0];
    const float* x_im    = (const float*)d_in[1];
    const float* wqkv_re = (const float*)d_in[2];
    const float* wqkv_im = (const float*)d_in[3];
    const float* wo_re   = (const float*)d_in[4];
    const float* wo_im   = (const float*)d_in[5];
    float* out = (float*)d_out;

    __nv_bfloat16 *xrH, *xrL, *xiH, *xiL;
    __nv_bfloat16 *wqrH, *wqrL, *wqiH, *wqiL;
    __nv_bfloat16 *worH, *worL, *woiH, *woiL;
    __nv_bfloat16 *arH, *arL, *aiH, *aiL;
    cudaGetSymbolAddress((void**)&xrH, g_xrH);   cudaGetSymbolAddress((void**)&xrL, g_xrL);
    cudaGetSymbolAddress((void**)&xiH, g_xiH);   cudaGetSymbolAddress((void**)&xiL, g_xiL);
    cudaGetSymbolAddress((void**)&wqrH, g_wqrH); cudaGetSymbolAddress((void**)&wqrL, g_wqrL);
    cudaGetSymbolAddress((void**)&wqiH, g_wqiH); cudaGetSymbolAddress((void**)&wqiL, g_wqiL);
    cudaGetSymbolAddress((void**)&worH, g_worH); cudaGetSymbolAddress((void**)&worL, g_worL);
    cudaGetSymbolAddress((void**)&woiH, g_woiH); cudaGetSymbolAddress((void**)&woiL, g_woiL);
    cudaGetSymbolAddress((void**)&arH, g_arH);   cudaGetSymbolAddress((void**)&arL, g_arL);
    cudaGetSymbolAddress((void**)&aiH, g_aiH);   cudaGetSymbolAddress((void**)&aiL, g_aiL);

    cudaFuncSetAttribute(cgemm_tc_kernel<true>,
                         cudaFuncAttributeMaxDynamicSharedMemorySize, G_SMEM);
    cudaFuncSetAttribute(cgemm_tc_kernel<false>,
                         cudaFuncAttributeMaxDynamicSharedMemorySize, G_SMEM);
    cudaFuncSetAttribute(attn_tc_kernel,
                         cudaFuncAttributeMaxDynamicSharedMemorySize, A_SMEM);

    // 1. rope table
    rope_table_kernel<<<(SEQ * D_HEAD + 255) / 256, 256>>>();

    // 2. complex hi/lo splits of inputs + weights
    split_cx_kernel<<<(XN / 4 + 255) / 256, 256>>>(x_re, x_im, xrH, xrL, xiH, xiL, XN / 4);
    split_cx_kernel<<<(WQN / 4 + 255) / 256, 256>>>(wqkv_re, wqkv_im, wqrH, wqrL, wqiH, wqiL, WQN / 4);
    split_cx_kernel<<<(WON / 4 + 255) / 256, 256>>>(wo_re, wo_im, worH, worL, woiH, woiL, WON / 4);

    // 3. QKV projection with fused RoPE + head-split + Q/K/V emit
    {
        dim3 grid(QKV_N / GBN, M_TOK / GBM);
        cgemm_tc_kernel<true><<<grid, 256, G_SMEM>>>(
            xrH, xrL, xiH, xiL, wqrH, wqrL, wqiH, wqiL,
            nullptr, nullptr, QKV_N, D_MODEL);
    }

    // 4. tensor-core flash attention (Q-hi in registers, 3-stage K/V pipeline)
    {
        dim3 grid(SEQ / 128, BHN);
        attn_tc_kernel<<<grid, 256, A_SMEM>>>();
    }

    // 5. output projection -> d_out
    {
        dim3 grid(D_MODEL / GBN, M_TOK / GBM);
        cgemm_tc_kernel<false><<<grid, 256, G_SMEM>>>(
            arH, arL, aiH, aiL, worH, worL, woiH, woiL,
            out, out + (size_t)M_TOK * D_MODEL, D_MODEL, D_MODEL);
    }
}

// round 17
// speedup vs baseline: 1.3759x; 1.3759x over previous
#include <cuda_runtime.h>
#include <cuda_bf16.h>
#include <cuda_fp16.h>
#include <math.h>
#include <stdint.h>

// Problem constants
#define D_MODEL 1024
#define N_HEADS 16
#define D_HEAD  64
#define BATCH   4
#define SEQ     512
#define M_TOK   (BATCH * SEQ)       // 2048
#define QKV_N   (3 * D_MODEL)       // 3072
#define BHN     (BATCH * N_HEADS)   // 64
#define QS      (BHN * SEQ * D_HEAD) // 2097152

// ---------------- device scratch (no runtime allocation allowed) ----------------
__device__ float g_rope_cos[SEQ * D_HEAD];
__device__ float g_rope_sin[SEQ * D_HEAD];

// fp16 operands for projection GEMMs: A single fp16, B (weights) fp16 hi/lo
#define XN   (M_TOK * D_MODEL)      // 2097152
#define WQN  (QKV_N * D_MODEL)      // 3145728
#define WON  (D_MODEL * D_MODEL)    // 1048576
__device__ __half g_xrF[XN],  g_xiF[XN];
__device__ __half g_wqrH[WQN], g_wqrL[WQN], g_wqiH[WQN], g_wqiL[WQN];
__device__ __half g_worH[WON], g_worL[WON], g_woiH[WON], g_woiL[WON];
__device__ __half g_arF[XN],  g_aiF[XN];          // attention output (A of out-proj)

// attention operands (written by fused QKV-GEMM epilogue)
// Q: single fp16 [bh][s][d], pre-scaled by 1/8.  K: fp16 hi/lo [bh][s][d].
// V: single fp16 [bh][d][s] dim-major (transposed, B-frag ready).
__device__ __half g_QrF[QS], g_QiF[QS];
__device__ __half g_KrH[QS], g_KrL[QS], g_KiH[QS], g_KiL[QS];
__device__ __half g_VrF[QS], g_ViF[QS];

// ================= PTX helpers (baseline ISA only — no tcgen05) =================
__device__ __forceinline__ uint32_t smem_u32(const void* p) {
    uint32_t a;
    asm("{ .reg .u64 t; cvta.to.shared.u64 t, %1; cvt.u32.u64 %0, t; }" : "=r"(a) : "l"(p));
    return a;
}
__device__ __forceinline__ void cp_async16(uint32_t dst, const void* src) {
    asm volatile("cp.async.cg.shared.global [%0], [%1], 16;" :: "r"(dst), "l"(src));
}
__device__ __forceinline__ void cp_commit() {
    asm volatile("cp.async.commit_group;" ::: "memory");
}
template <int N> __device__ __forceinline__ void cp_wait() {
    asm volatile("cp.async.wait_group %0;" :: "n"(N) : "memory");
}
__device__ __forceinline__ void ldsm_x4(uint32_t* r, uint32_t a) {
    asm volatile("ldmatrix.sync.aligned.m8n8.x4.shared.b16 {%0,%1,%2,%3}, [%4];"
                 : "=r"(r[0]), "=r"(r[1]), "=r"(r[2]), "=r"(r[3]) : "r"(a));
}
// D += A(16x16 f16, row) * B(16x8 f16, col), fp32 accumulate
__device__ __forceinline__ void mma_f16(float* c, const uint32_t* a, const uint32_t* b) {
    asm volatile(
        "mma.sync.aligned.m16n8k16.row.col.f32.f16.f16.f32 "
        "{%0,%1,%2,%3}, {%4,%5,%6,%7}, {%8,%9}, {%0,%1,%2,%3};"
        : "+f"(c[0]), "+f"(c[1]), "+f"(c[2]), "+f"(c[3])
        : "r"(a[0]), "r"(a[1]), "r"(a[2]), "r"(a[3]), "r"(b[0]), "r"(b[1]));
}
__device__ __forceinline__ void hsplit(float v, __half& h, __half& l) {
    h = __float2half_rn(v);
    l = __float2half_rn(v - __half2float(h));
}
__device__ __forceinline__ uint32_t packh2f(__half a, __half b) {
    __half2 t{a, b};
    return *reinterpret_cast<uint32_t*>(&t);
}
__device__ __forceinline__ uint32_t packh2(float a, float b) {
    __half2 t{__float2half_rn(a), __float2half_rn(b)};
    return *reinterpret_cast<uint32_t*>(&t);
}
#define SGNX2 0x80008000u

// ---------------- kernel 1: RoPE rotor table ----------------
__global__ void rope_table_kernel() {
    int i = blockIdx.x * blockDim.x + threadIdx.x;
    if (i >= SEQ * D_HEAD) return;
    int s = i / D_HEAD;
    int d = i % D_HEAD;
    float inv_freq = powf(10000.0f, -(float)d / (float)D_HEAD);
    float ang = (float)s * inv_freq;
    float sn, cs;
    sincosf(ang, &sn, &cs);
    g_rope_cos[i] = cs;
    g_rope_sin[i] = sn;
}

// ---------------- kernel 1b: complex -> single fp16 (A operands) ----------------
__global__ void split_f16s_kernel(const float* __restrict__ re, const float* __restrict__ im,
                                  __half* __restrict__ rF, __half* __restrict__ iF, int n4) {
    int i = blockIdx.x * blockDim.x + threadIdx.x;
    if (i >= n4) return;
    float4 vr = ((const float4*)re)[i];
    float4 vi = ((const float4*)im)[i];
    ((uint32_t*)rF)[i * 2 + 0] = packh2(vr.x, vr.y);
    ((uint32_t*)rF)[i * 2 + 1] = packh2(vr.z, vr.w);
    ((uint32_t*)iF)[i * 2 + 0] = packh2(vi.x, vi.y);
    ((uint32_t*)iF)[i * 2 + 1] = packh2(vi.z, vi.w);
}

// ---------------- kernel 1c: complex -> fp16 hi/lo (B operands) ----------------
__global__ void split_f16hl_kernel(const float* __restrict__ re, const float* __restrict__ im,
                                   __half* __restrict__ rH, __half* __restrict__ rL,
                                   __half* __restrict__ iH, __half* __restrict__ iL, int n4) {
    int i = blockIdx.x * blockDim.x + threadIdx.x;
    if (i >= n4) return;
    float4 vr = ((const float4*)re)[i];
    float4 vi = ((const float4*)im)[i];
    __half h0, h1, h2, h3, l0, l1, l2, l3;
    hsplit(vr.x, h0, l0); hsplit(vr.y, h1, l1); hsplit(vr.z, h2, l2); hsplit(vr.w, h3, l3);
    ((uint32_t*)rH)[i * 2 + 0] = packh2f(h0, h1);
    ((uint32_t*)rH)[i * 2 + 1] = packh2f(h2, h3);
    ((uint32_t*)rL)[i * 2 + 0] = packh2f(l0, l1);
    ((uint32_t*)rL)[i * 2 + 1] = packh2f(l2, l3);
    hsplit(vi.x, h0, l0); hsplit(vi.y, h1, l1); hsplit(vi.z, h2, l2); hsplit(vi.w, h3, l3);
    ((uint32_t*)iH)[i * 2 + 0] = packh2f(h0, h1);
    ((uint32_t*)iH)[i * 2 + 1] = packh2f(h2, h3);
    ((uint32_t*)iL)[i * 2 + 0] = packh2f(l0, l1);
    ((uint32_t*)iL)[i * 2 + 1] = packh2f(l2, l3);
}

// ---------------- kernel 2: fp16 mma.sync complex GEMM  C = A @ B^T ----------------
// A single fp16 (2 comps), B fp16 hi/lo (4 comps). 8 MMA per micro-tile:
//   Cre = Ar(BrH+BrL) - Ai(BiH+BiL)   (neg-Bi frags)
//   Cim = Ar(BiH+BiL) + Ai(BrH+BrL)
// CTA tile 128x128, K-stage 32, 2-stage cp.async, 8 warps (4m x 2n), warp tile 32x64.
// FUSE_ROPE epilogue: RoPE + head-split + Q fp16 (pre-scaled) + K fp16 hi/lo + V fp16.
#define GBM 128
#define GBN 128
#define GBK 32
#define GPITCHB 80
#define A_COMP_B (GBM * GPITCHB)              // 10240
#define B_COMP_B (GBN * GPITCHB)              // 10240
#define STAGE_B  (2 * A_COMP_B + 4 * B_COMP_B) // 61440
#define G_SMEM   (2 * STAGE_B)                 // 122880

template <bool FUSE_ROPE>
__global__ __launch_bounds__(256, 1) void cgemm_tc_kernel(
    const __half* __restrict__ ArF, const __half* __restrict__ AiF,
    const __half* __restrict__ BrH, const __half* __restrict__ BrL,
    const __half* __restrict__ BiH, const __half* __restrict__ BiL,
    float* __restrict__ Cre, float* __restrict__ Cim,
    int N, int K)
{
    extern __shared__ __align__(128) char smem[];
    const uint32_t sb = smem_u32(smem);
    const int tid = threadIdx.x;
    const int lane = tid & 31;
    const int wid = tid >> 5;
    const int wm = wid & 3;
    const int wn = wid >> 2;
    const int m0 = blockIdx.y * GBM;
    const int n0 = blockIdx.x * GBN;

    const __half* Ap[2] = {ArF, AiF};
    const __half* Bp[4] = {BrH, BrL, BiH, BiL};

    auto load_stage = [&](int st, int k0) {
        uint32_t base = sb + st * STAGE_B;
#pragma unroll
        for (int i = 0; i < 4; i++) {                 // A: 1024 16B chunks
            int idx = tid + i * 256;
            int comp = idx >> 9;
            int rem = idx & 511;
            int row = rem >> 2;
            int ch = rem & 3;
            cp_async16(base + comp * A_COMP_B + row * GPITCHB + ch * 16,
                       Ap[comp] + (size_t)(m0 + row) * K + k0 + ch * 8);
        }
        uint32_t bbase = base + 2 * A_COMP_B;
#pragma unroll
        for (int i = 0; i < 8; i++) {                 // B: 2048 16B chunks
            int idx = tid + i * 256;
            int comp = idx >> 9;
            int rem = idx & 511;
            int row = rem >> 2;
            int ch = rem & 3;
            cp_async16(bbase + comp * B_COMP_B + row * GPITCHB + ch * 16,
                       Bp[comp] + (size_t)(n0 + row) * K + k0 + ch * 8);
        }
        cp_commit();
    };

    float cre[2][8][4];
    float cim[2][8][4];
#pragma unroll
    for (int mt = 0; mt < 2; mt++)
#pragma unroll
        for (int nt = 0; nt < 8; nt++)
#pragma unroll
            for (int q = 0; q < 4; q++) { cre[mt][nt][q] = 0.f; cim[mt][nt][q] = 0.f; }

    const int NC = K / GBK;
    load_stage(0, 0);

    const uint32_t krow = ((lane >> 4) & 1) * 8 + (lane & 7);
    const uint32_t koff = ((lane >> 3) & 1) * 16;

    for (int c = 0; c < NC; c++) {
        if (c + 1 < NC) { load_stage((c + 1) & 1, (c + 1) * GBK); cp_wait<1>(); }
        else            { cp_wait<0>(); }
        __syncthreads();

        const uint32_t abase = sb + (c & 1) * STAGE_B;
        const uint32_t bbase = abase + 2 * A_COMP_B;

#pragma unroll
        for (int ks = 0; ks < 2; ks++) {
            uint32_t af[2][2][4];
#pragma unroll
            for (int comp = 0; comp < 2; comp++)
#pragma unroll
                for (int mt = 0; mt < 2; mt++) {
                    uint32_t addr = abase + comp * A_COMP_B
                        + (uint32_t)(wm * 32 + mt * 16 + (lane & 15)) * GPITCHB
                        + ks * 32 + (lane >> 4) * 16;
                    ldsm_x4(af[comp][mt], addr);
                }
#pragma unroll
            for (int nt16 = 0; nt16 < 4; nt16++) {
                uint32_t bfr[4][4];
                uint32_t baddr = bbase
                    + (uint32_t)(wn * 64 + nt16 * 16 + krow) * GPITCHB
                    + ks * 32 + koff;
#pragma unroll
                for (int comp = 0; comp < 4; comp++)
                    ldsm_x4(bfr[comp], baddr + comp * B_COMP_B);
#pragma unroll
                for (int hf = 0; hf < 2; hf++) {
                    int nt = nt16 * 2 + hf;
                    const uint32_t* bRH = bfr[0] + hf * 2;
                    const uint32_t* bRL = bfr[1] + hf * 2;
                    const uint32_t* bIH = bfr[2] + hf * 2;
                    const uint32_t* bIL = bfr[3] + hf * 2;
                    uint32_t nIH[2] = {bIH[0] ^ SGNX2, bIH[1] ^ SGNX2};
                    uint32_t nIL[2] = {bIL[0] ^ SGNX2, bIL[1] ^ SGNX2};
#pragma unroll
                    for (int mt = 0; mt < 2; mt++) {
                        float* cr = cre[mt][nt];
                        float* ci = cim[mt][nt];
                        mma_f16(cr, af[0][mt], bRH);
                        mma_f16(cr, af[0][mt], bRL);
                        mma_f16(cr, af[1][mt], nIH);
                        mma_f16(cr, af[1][mt], nIL);
                        mma_f16(ci, af[0][mt], bIH);
                        mma_f16(ci, af[0][mt], bIL);
                        mma_f16(ci, af[1][mt], bRH);
                        mma_f16(ci, af[1][mt], bRL);
                    }
                }
            }
        }
        __syncthreads();
    }

    // ---- epilogue ----
#pragma unroll
    for (int mt = 0; mt < 2; mt++) {
        int row0 = m0 + wm * 32 + mt * 16 + (lane >> 2);
#pragma unroll
        for (int nt = 0; nt < 8; nt++) {
            int col = n0 + wn * 64 + nt * 8 + (lane & 3) * 2;
            if (!FUSE_ROPE) {
                *(float2*)(Cre + (size_t)row0 * N + col) = {cre[mt][nt][0], cre[mt][nt][1]};
                *(float2*)(Cre + (size_t)(row0 + 8) * N + col) = {cre[mt][nt][2], cre[mt][nt][3]};
                *(float2*)(Cim + (size_t)row0 * N + col) = {cim[mt][nt][0], cim[mt][nt][1]};
                *(float2*)(Cim + (size_t)(row0 + 8) * N + col) = {cim[mt][nt][2], cim[mt][nt][3]};
            } else {
                int sec = col >> 10;          // 0=Q, 1=K, 2=V
                int hd = col & 1023;
                int h = hd >> 6;
                int d = hd & 63;
#pragma unroll
                for (int half = 0; half < 2; half++) {
                    int tkn = row0 + half * 8;
                    int b = tkn >> 9;
                    int s = tkn & 511;
                    int bh = (b << 4) + h;
                    float re0 = cre[mt][nt][half * 2 + 0];
                    float re1 = cre[mt][nt][half * 2 + 1];
                    float im0 = cim[mt][nt][half * 2 + 0];
                    float im1 = cim[mt][nt][half * 2 + 1];
                    if (sec == 2) {
                        size_t j = (size_t)bh * 32768 + (size_t)d * 512 + s;
                        g_VrF[j] = __float2half_rn(re0);
                        g_ViF[j] = __float2half_rn(im0);
                        g_VrF[j + 512] = __float2half_rn(re1);
                        g_ViF[j + 512] = __float2half_rn(im1);
                    } else {
                        float2 rc = *(const float2*)(g_rope_cos + s * 64 + d);
                        float2 rs = *(const float2*)(g_rope_sin + s * 64 + d);
                        float ar0 = re0 * rc.x - im0 * rs.x;
                        float ai0 = re0 * rs.x + im0 * rc.x;
                        float ar1 = re1 * rc.y - im1 * rs.y;
                        float ai1 = re1 * rs.y + im1 * rc.y;
                        size_t i = (size_t)bh * 32768 + s * 64 + d;
                        if (sec == 0) {
                            // Q: fold 1/sqrt(Dh), emit single fp16
                            *(uint32_t*)(g_QrF + i) = packh2(ar0 * 0.125f, ar1 * 0.125f);
                            *(uint32_t*)(g_QiF + i) = packh2(ai0 * 0.125f, ai1 * 0.125f);
                        } else {
                            // K: fp16 hi/lo
                            __half h0, l0, h1, l1;
                            hsplit(ar0, h0, l0); hsplit(ar1, h1, l1);
                            *(uint32_t*)(g_KrH + i) = packh2f(h0, h1);
                            *(uint32_t*)(g_KrL + i) = packh2f(l0, l1);
                            hsplit(ai0, h0, l0); hsplit(ai1, h1, l1);
                            *(uint32_t*)(g_KiH + i) = packh2f(h0, h1);
                            *(uint32_t*)(g_KiL + i) = packh2f(l0, l1);
                        }
                    }
                }
            }
        }
    }
}

// ---------------- kernel 4: tensor-core flash attention (complex, fp16) ----------------
// CTA: 128 queries x one (b,h). 8 warps, warp w owns rows w*16..w*16+15.
// Q single fp16 entirely in registers (staged via KV buffer 1, loaded once).
// Scores: Q fp16 x K fp16 hi/lo = 8 MMA/micro.  PV: fp16 single = 4 MMA/micro.
#define AP    144
#define KCOMP (64 * AP)                    // 9216
#define ASTAGE   (6 * KCOMP)               // 4 K comps + 2 V comps
#define A_SMEM   (2 * ASTAGE)              // 110592

__global__ __launch_bounds__(256, 1) void attn_tc_kernel() {
    extern __shared__ __align__(128) char smem[];
    const uint32_t sb = smem_u32(smem);
    const int tid = threadIdx.x;
    const int lane = tid & 31;
    const int w = tid >> 5;
    const int grp = lane >> 2;
    const int tq = lane & 3;
    const int q0 = blockIdx.x * 128;
    const int bh = blockIdx.y;

    const __half* gK[4] = {g_KrH, g_KrL, g_KiH, g_KiL};
    const __half* gV[2] = {g_VrF, g_ViF};
    const size_t hbQ = (size_t)bh * (SEQ * 64);

    // ---- prologue: stage Q (2 comps, 128 rows) into KV buffer 1 ----
    {
        const __half* gQ[2] = {g_QrF, g_QiF};
        uint32_t qstage = sb + ASTAGE;
#pragma unroll
        for (int it = 0; it < 8; it++) {
            int idx = tid + it * 256;
            int comp = idx >> 10;          // 0..1
            int rem = idx & 1023;
            int row = rem >> 3;
            int ch = rem & 7;
            cp_async16(qstage + comp * (2 * KCOMP) + row * AP + ch * 16,
                       gQ[comp] + hbQ + (size_t)(q0 + row) * 64 + ch * 8);
        }
        cp_commit();
    }

    auto load_stage = [&](int st, int c0) {
        uint32_t base = sb + st * ASTAGE;
#pragma unroll
        for (int it = 0; it < 12; it++) {
            int idx = tid + it * 256;
            int comp = idx >> 9;              // 0..5
            int rem = idx & 511;
            int row = rem >> 3;
            int ch = rem & 7;
            const void* src;
            if (comp < 4) src = gK[comp] + hbQ + (size_t)(c0 + row) * 64 + ch * 8;
            else          src = gV[comp - 4] + hbQ + (size_t)row * SEQ + c0 + ch * 8;
            cp_async16(base + comp * KCOMP + row * AP + ch * 16, src);
        }
        cp_commit();
    };
    load_stage(0, 0);           // kc0 -> buf0
    cp_wait<1>();               // Q staging done
    __syncthreads();

    // Q fragments -> registers (reused across all 8 key-blocks)
    uint32_t Qr[4][4], Qi[4][4];
    {
        uint32_t qstage = sb + ASTAGE;
#pragma unroll
        for (int ks = 0; ks < 4; ks++) {
            uint32_t qa = (uint32_t)(w * 16 + (lane & 15)) * AP + ks * 32 + (lane >> 4) * 16;
            ldsm_x4(Qr[ks], qstage + qa);
            ldsm_x4(Qi[ks], qstage + 2 * KCOMP + qa);
        }
    }
    __syncthreads();            // buf1 free for K/V after all warps read Q

    float or_[8][4], oi_[8][4];
#pragma unroll
    for (int nt = 0; nt < 8; nt++)
#pragma unroll
        for (int q = 0; q < 4; q++) { or_[nt][q] = 0.f; oi_[nt][q] = 0.f; }
    float m0 = -1e30f, m1 = -1e30f, l0 = 0.f, l1 = 0.f;

    const uint32_t krow = ((lane >> 4) & 1) * 8 + (lane & 7);
    const uint32_t koff = ((lane >> 3) & 1) * 16;

    for (int kc = 0; kc < 8; kc++) {
        if (kc + 1 < 8) { load_stage((kc + 1) & 1, (kc + 1) * 64); cp_wait<1>(); }
        else            { cp_wait<0>(); }
        __syncthreads();
        const uint32_t stg = sb + (kc & 1) * ASTAGE;

        float sre[8][4], sim[8][4];
#pragma unroll
        for (int nt = 0; nt < 8; nt++)
#pragma unroll
            for (int q = 0; q < 4; q++) { sre[nt][q] = 0.f; sim[nt][q] = 0.f; }

#pragma unroll
        for (int ks = 0; ks < 4; ks++) {
#pragma unroll
            for (int nt16 = 0; nt16 < 4; nt16++) {
                uint32_t kb = stg + (uint32_t)(nt16 * 16 + krow) * AP + ks * 32 + koff;
                uint32_t krH[4], krL[4], kiH[4], kiL[4];
                ldsm_x4(krH, kb + 0 * KCOMP);
                ldsm_x4(krL, kb + 1 * KCOMP);
                ldsm_x4(kiH, kb + 2 * KCOMP);
                ldsm_x4(kiL, kb + 3 * KCOMP);
#pragma unroll
                for (int hf = 0; hf < 2; hf++) {
                    int nt = nt16 * 2 + hf;
                    const uint32_t* bRH = krH + hf * 2;
                    const uint32_t* bRL = krL + hf * 2;
                    const uint32_t* bIH = kiH + hf * 2;
                    const uint32_t* bIL = kiL + hf * 2;
                    uint32_t nIH[2] = {bIH[0] ^ SGNX2, bIH[1] ^ SGNX2};
                    uint32_t nIL[2] = {bIL[0] ^ SGNX2, bIL[1] ^ SGNX2};
                    // re = Qr*Kr + Qi*Ki
                    mma_f16(sre[nt], Qr[ks], bRH);
                    mma_f16(sre[nt], Qr[ks], bRL);
                    mma_f16(sre[nt], Qi[ks], bIH);
                    mma_f16(sre[nt], Qi[ks], bIL);
                    // im = Qi*Kr - Qr*Ki
                    mma_f16(sim[nt], Qi[ks], bRH);
                    mma_f16(sim[nt], Qi[ks], bRL);
                    mma_f16(sim[nt], Qr[ks], nIH);
                    mma_f16(sim[nt], Qr[ks], nIL);
                }
            }
        }

        // ---- online softmax (scale already folded into Q) ----
        float cx0 = -1e30f, cx1 = -1e30f;
#pragma unroll
        for (int nt = 0; nt < 8; nt++) {
            cx0 = fmaxf(cx0, fmaxf(sre[nt][0], sre[nt][1]));
            cx1 = fmaxf(cx1, fmaxf(sre[nt][2], sre[nt][3]));
        }
        cx0 = fmaxf(cx0, __shfl_xor_sync(0xffffffffu, cx0, 1));
        cx0 = fmaxf(cx0, __shfl_xor_sync(0xffffffffu, cx0, 2));
        cx1 = fmaxf(cx1, __shfl_xor_sync(0xffffffffu, cx1, 1));
        cx1 = fmaxf(cx1, __shfl_xor_sync(0xffffffffu, cx1, 2));

        float nm0 = fmaxf(m0, cx0), nm1 = fmaxf(m1, cx1);
        float al0 = __expf(m0 - nm0), al1 = __expf(m1 - nm1);
        m0 = nm0; m1 = nm1;

        float rs0 = 0.f, rs1 = 0.f;
#pragma unroll
        for (int nt = 0; nt < 8; nt++) {
            float p0 = __expf(sre[nt][0] - nm0);
            float p1 = __expf(sre[nt][1] - nm0);
            float p2 = __expf(sre[nt][2] - nm1);
            float p3 = __expf(sre[nt][3] - nm1);
            rs0 += p0 + p1; rs1 += p2 + p3;
            float sn, cs;
            __sincosf(sim[nt][0], &sn, &cs); sre[nt][0] = p0 * cs; sim[nt][0] = p0 * sn;
            __sincosf(sim[nt][1], &sn, &cs); sre[nt][1] = p1 * cs; sim[nt][1] = p1 * sn;
            __sincosf(sim[nt][2], &sn, &cs); sre[nt][2] = p2 * cs; sim[nt][2] = p2 * sn;
            __sincosf(sim[nt][3], &sn, &cs); sre[nt][3] = p3 * cs; sim[nt][3] = p3 * sn;
        }
        rs0 += __shfl_xor_sync(0xffffffffu, rs0, 1);
        rs0 += __shfl_xor_sync(0xffffffffu, rs0, 2);
        rs1 += __shfl_xor_sync(0xffffffffu, rs1, 1);
        rs1 += __shfl_xor_sync(0xffffffffu, rs1, 2);
        l0 = l0 * al0 + rs0;
        l1 = l1 * al1 + rs1;
#pragma unroll
        for (int nt = 0; nt < 8; nt++) {
            or_[nt][0] *= al0; or_[nt][1] *= al0; or_[nt][2] *= al1; or_[nt][3] *= al1;
            oi_[nt][0] *= al0; oi_[nt][1] *= al0; oi_[nt][2] *= al1; oi_[nt][3] *= al1;
        }

        // weight C-frags -> fp16 A-frags
        uint32_t wcF[4][4], wsF[4][4];
#pragma unroll
        for (int t = 0; t < 4; t++)
#pragma unroll
            for (int r = 0; r < 4; r++) {
                int nt = 2 * t + (r >> 1);
                int e = (r & 1) * 2;
                wcF[t][r] = packh2(sre[nt][e], sre[nt][e + 1]);
                wsF[t][r] = packh2(sim[nt][e], sim[nt][e + 1]);
            }

        // PV (fp16): out_r += Wc*Vr - Ws*Vi ; out_i += Wc*Vi + Ws*Vr
#pragma unroll
        for (int ks = 0; ks < 4; ks++) {
#pragma unroll
            for (int nt16 = 0; nt16 < 4; nt16++) {
                uint32_t vb = stg + (uint32_t)(nt16 * 16 + krow) * AP + ks * 32 + koff;
                uint32_t vrF[4], viF[4];
                ldsm_x4(vrF, vb + 4 * KCOMP);
                ldsm_x4(viF, vb + 5 * KCOMP);
#pragma unroll
                for (int hf = 0; hf < 2; hf++) {
                    int nt = nt16 * 2 + hf;
                    const uint32_t* bRF = vrF + hf * 2;
                    const uint32_t* bIF = viF + hf * 2;
                    uint32_t nIF[2] = {bIF[0] ^ SGNX2, bIF[1] ^ SGNX2};
                    mma_f16(or_[nt], wcF[ks], bRF);
                    mma_f16(or_[nt], wsF[ks], nIF);
                    mma_f16(oi_[nt], wcF[ks], bIF);
                    mma_f16(oi_[nt], wsF[ks], bRF);
                }
            }
        }
        __syncthreads();
    }

    // ---- epilogue: emit single fp16 (A operand of output projection) ----
    int b = bh >> 4;
    int h = bh & 15;
    float inv0 = 1.0f / l0, inv1 = 1.0f / l1;
    int qr0 = q0 + w * 16 + grp;
#pragma unroll
    for (int nt = 0; nt < 8; nt++) {
        int col = h * 64 + nt * 8 + tq * 2;
        size_t r0 = (size_t)(b * SEQ + qr0) * D_MODEL + col;
        size_t r1 = (size_t)(b * SEQ + qr0 + 8) * D_MODEL + col;
        *(uint32_t*)(g_arF + r0) = packh2(or_[nt][0] * inv0, or_[nt][1] * inv0);
        *(uint32_t*)(g_arF + r1) = packh2(or_[nt][2] * inv1, or_[nt][3] * inv1);
        *(uint32_t*)(g_aiF + r0) = packh2(oi_[nt][0] * inv0, oi_[nt][1] * inv0);
        *(uint32_t*)(g_aiF + r1) = packh2(oi_[nt][2] * inv1, oi_[nt][3] * inv1);
    }
}

// ---------------- launch ----------------
extern "C" void kernel_launch(void* const* d_in, const int* in_sizes, int n_in,
                              void* d_out, int out_size) {
    (void)in_sizes; (void)n_in; (void)out_size;
    const float* x_re    = (const float*)d_in[0];
    const float* x_im    = (const float*)d_in[1];
    const float* wqkv_re = (const float*)d_in[2];
    const float* wqkv_im = (const float*)d_in[3];
    const float* wo_re   = (const float*)d_in[4];
    const float* wo_im   = (const float*)d_in[5];
    float* out = (float*)d_out;

    __half *xrF, *xiF, *arF, *aiF;
    __half *wqrH, *wqrL, *wqiH, *wqiL;
    __half *worH, *worL, *woiH, *woiL;
    cudaGetSymbolAddress((void**)&xrF, g_xrF);   cudaGetSymbolAddress((void**)&xiF, g_xiF);
    cudaGetSymbolAddress((void**)&arF, g_arF);   cudaGetSymbolAddress((void**)&aiF, g_aiF);
    cudaGetSymbolAddress((void**)&wqrH, g_wqrH); cudaGetSymbolAddress((void**)&wqrL, g_wqrL);
    cudaGetSymbolAddress((void**)&wqiH, g_wqiH); cudaGetSymbolAddress((void**)&wqiL, g_wqiL);
    cudaGetSymbolAddress((void**)&worH, g_worH); cudaGetSymbolAddress((void**)&worL, g_worL);
    cudaGetSymbolAddress((void**)&woiH, g_woiH); cudaGetSymbolAddress((void**)&woiL, g_woiL);

    cudaFuncSetAttribute(cgemm_tc_kernel<true>,
                         cudaFuncAttributeMaxDynamicSharedMemorySize, G_SMEM);
    cudaFuncSetAttribute(cgemm_tc_kernel<false>,
                         cudaFuncAttributeMaxDynamicSharedMemorySize, G_SMEM);
    cudaFuncSetAttribute(attn_tc_kernel,
                         cudaFuncAttributeMaxDynamicSharedMemorySize, A_SMEM);

    // 1. rope table
    rope_table_kernel<<<(SEQ * D_HEAD + 255) / 256, 256>>>();

    // 2. fp16 operand prep: x -> single fp16, weights -> fp16 hi/lo
    split_f16s_kernel<<<(XN / 4 + 255) / 256, 256>>>(x_re, x_im, xrF, xiF, XN / 4);
    split_f16hl_kernel<<<(WQN / 4 + 255) / 256, 256>>>(wqkv_re, wqkv_im,
                                                       wqrH, wqrL, wqiH, wqiL, WQN / 4);
    split_f16hl_kernel<<<(WON / 4 + 255) / 256, 256>>>(wo_re, wo_im,
                                                       worH, worL, woiH, woiL, WON / 4);

    // 3. QKV projection with fused RoPE + head-split + Q/K/V emit
    {
        dim3 grid(QKV_N / GBN, M_TOK / GBM);
        cgemm_tc_kernel<true><<<grid, 256, G_SMEM>>>(
            xrF, xiF, wqrH, wqrL, wqiH, wqiL,
            nullptr, nullptr, QKV_N, D_MODEL);
    }

    // 4. tensor-core flash attention (Q in registers, fp16 scores + PV)
    {
        dim3 grid(SEQ / 128, BHN);
        attn_tc_kernel<<<grid, 256, A_SMEM>>>();
    }

    // 5. output projection -> d_out
    {
        dim3 grid(D_MODEL / GBN, M_TOK / GBM);
        cgemm_tc_kernel<false><<<grid, 256, G_SMEM>>>(
            arF, aiF, worH, worL, woiH, woiL,
            out, out + (size_t)M_TOK * D_MODEL, D_MODEL, D_MODEL);
    }
}